// round 14
// baseline (speedup 1.0000x reference)
#include <cuda_runtime.h>
#include <cuda_bf16.h>
#include <cstdint>
#include <math.h>

#define S_LEN   2048
#define B_SZ    2
#define NH      16
#define HD      128
#define M_TOT   (B_SZ * S_LEN)     /* 4096 */
#define HIDDEN  2048
#define LATENT  512

// ---------------- scratch (device globals: no allocation allowed) ----------------
__device__ float g_k_rope[M_TOT * 1024];          // fp32 rope-k (pre-RoPE)
__device__ float g_kvout [M_TOT * 3072];          // cols 0-1023: k_half, 1024-3071: V
__device__ float g_qout  [M_TOT * 2048];          // cols 0-1023: q_half, 1024-2047: q_rope
__device__ float g_cos   [S_LEN * 32];
__device__ float g_sin   [S_LEN * 32];

// bf16 hi/lo split buffers
__device__ __nv_bfloat16 g_xb_hi[M_TOT * HIDDEN];   // x split; later reused for attention output Y
__device__ __nv_bfloat16 g_xb_lo[M_TOT * HIDDEN];
__device__ __nv_bfloat16 g_lat_hi[M_TOT * 1024];    // cols 0-511: kv latent, 512-1023: q latent
__device__ __nv_bfloat16 g_lat_lo[M_TOT * 1024];

// attention operands (bf16 hi/lo)
__device__ __nv_bfloat16 g_Qh[M_TOT * HIDDEN];
__device__ __nv_bfloat16 g_Ql[M_TOT * HIDDEN];
__device__ __nv_bfloat16 g_Kh[M_TOT * HIDDEN];
__device__ __nv_bfloat16 g_Kl[M_TOT * HIDDEN];
__device__ __nv_bfloat16 g_Vth[B_SZ * NH * HD * S_LEN];  // [b][h][d][s]
__device__ __nv_bfloat16 g_Vtl[B_SZ * NH * HD * S_LEN];

// packed transposed weights [N,K] bf16 hi/lo
#define OFF_L1     0
#define OFF_L2KV   4194304
#define OFF_L2Q    5767168
#define OFF_O      6815744
#define W_POOL     11010048
#define L2Q_DELTA  (OFF_L2Q - OFF_L2KV)   /* 1572864 */
__device__ __nv_bfloat16 g_wb_hi[W_POOL];
__device__ __nv_bfloat16 g_wb_lo[W_POOL];

// ================= helpers =================
__device__ __forceinline__ uint32_t smem_u32(const void* p) {
    uint32_t a;
    asm("{ .reg .u64 t; cvta.to.shared.u64 t, %1; cvt.u32.u64 %0, t; }" : "=r"(a) : "l"(p));
    return a;
}

__device__ __forceinline__ void ldmx4(uint32_t* r, uint32_t addr) {
    asm volatile("ldmatrix.sync.aligned.m8n8.x4.shared.b16 {%0,%1,%2,%3}, [%4];"
        : "=r"(r[0]), "=r"(r[1]), "=r"(r[2]), "=r"(r[3]) : "r"(addr));
}

__device__ __forceinline__ void mma16816(float* c, const uint32_t* a, uint32_t b0, uint32_t b1) {
    asm volatile(
        "mma.sync.aligned.m16n8k16.row.col.f32.bf16.bf16.f32 "
        "{%0,%1,%2,%3}, {%4,%5,%6,%7}, {%8,%9}, {%0,%1,%2,%3};"
        : "+f"(c[0]), "+f"(c[1]), "+f"(c[2]), "+f"(c[3])
        : "r"(a[0]), "r"(a[1]), "r"(a[2]), "r"(a[3]), "r"(b0), "r"(b1));
}

__device__ __forceinline__ void cp16(uint32_t dst, const void* src) {
    unsigned long long g = (unsigned long long)__cvta_generic_to_global(src);
    asm volatile("cp.async.cg.shared.global [%0], [%1], 16;" :: "r"(dst), "l"(g) : "memory");
}

__device__ __forceinline__ void bsplit2(float a, float b, uint32_t& hi, uint32_t& lo) {
    __nv_bfloat162 h, l;
    h.x = __float2bfloat16(a); l.x = __float2bfloat16(a - __bfloat162float(h.x));
    h.y = __float2bfloat16(b); l.y = __float2bfloat16(b - __bfloat162float(h.y));
    hi = *(uint32_t*)&h; lo = *(uint32_t*)&l;
}

// ================= mega conversion kernel =================
// blocks [0,10752): weight transpose+split.  [10752,11008): RoPE table.
// [11008,19200): x -> bf16 hi/lo split.
__global__ void wconv_all_kernel(
    const float* __restrict__ W_kv_d, const float* __restrict__ W_q_d,
    const float* __restrict__ W_rope_k, const float* __restrict__ W_k_u,
    const float* __restrict__ W_v_u, const float* __restrict__ W_q_u,
    const float* __restrict__ W_rope_q, const float* __restrict__ W_o,
    __nv_bfloat16* __restrict__ hi, __nv_bfloat16* __restrict__ lo,
    float* __restrict__ cosT, float* __restrict__ sinT,
    const float* __restrict__ x,
    __nv_bfloat16* __restrict__ xhi, __nv_bfloat16* __restrict__ xlo)
{
    int tb = blockIdx.x;
    int tid = threadIdx.y * 32 + threadIdx.x;
    if (tb >= 11008) {   // x split: 8192 blocks x 256 threads x float4
        int i = (tb - 11008) * 256 + tid;
        float4 v = ((const float4*)x)[i];
        __nv_bfloat162 h01, h23, l01, l23;
        h01.x = __float2bfloat16(v.x); l01.x = __float2bfloat16(v.x - __bfloat162float(h01.x));
        h01.y = __float2bfloat16(v.y); l01.y = __float2bfloat16(v.y - __bfloat162float(h01.y));
        h23.x = __float2bfloat16(v.z); l23.x = __float2bfloat16(v.z - __bfloat162float(h23.x));
        h23.y = __float2bfloat16(v.w); l23.y = __float2bfloat16(v.w - __bfloat162float(h23.y));
        uint2 hv, lv;
        hv.x = *(uint32_t*)&h01; hv.y = *(uint32_t*)&h23;
        lv.x = *(uint32_t*)&l01; lv.y = *(uint32_t*)&l23;
        ((uint2*)xhi)[i] = hv;
        ((uint2*)xlo)[i] = lv;
        return;
    }
    if (tb >= 10752) {   // RoPE table: 256 blocks x 256 threads = 65536
        int idx = (tb - 10752) * 256 + tid;
        int s = idx >> 5;
        int i = idx & 31;
        double inv = exp(-((double)i / 32.0) * log(10000.0));
        double a   = (double)s * inv;
        cosT[idx] = (float)cos(a);
        sinT[idx] = (float)sin(a);
        return;
    }
    __shared__ float t[32][33];
    const float* W; int K, N; size_t off;
    if      (tb <  1024) { W = W_kv_d;   K = 2048; N =  512; off = OFF_L1;                    }
    else if (tb <  2048) { W = W_q_d;    K = 2048; N =  512; off = OFF_L1 + 1048576;  tb -= 1024; }
    else if (tb <  4096) { W = W_rope_k; K = 2048; N = 1024; off = OFF_L1 + 2097152;  tb -= 2048; }
    else if (tb <  4608) { W = W_k_u;    K =  512; N = 1024; off = OFF_L2KV;          tb -= 4096; }
    else if (tb <  5632) { W = W_v_u;    K =  512; N = 2048; off = OFF_L2KV + 524288; tb -= 4608; }
    else if (tb <  6144) { W = W_q_u;    K =  512; N = 1024; off = OFF_L2Q;           tb -= 5632; }
    else if (tb <  6656) { W = W_rope_q; K =  512; N = 1024; off = OFF_L2Q + 524288;  tb -= 6144; }
    else                 { W = W_o;      K = 2048; N = 2048; off = OFF_O;             tb -= 6656; }
    int ntn = N >> 5;
    int n0 = (tb % ntn) << 5, k0 = (tb / ntn) << 5;
    int tx = threadIdx.x, ty = threadIdx.y;
    for (int j = ty; j < 32; j += 8)
        t[j][tx] = W[(size_t)(k0 + j) * N + n0 + tx];
    __syncthreads();
    for (int j = ty; j < 32; j += 8) {
        float v = t[tx][j];
        __nv_bfloat16 h = __float2bfloat16(v);
        size_t o = off + (size_t)(n0 + j) * K + k0 + tx;
        hi[o] = h;
        lo[o] = __float2bfloat16(v - __bfloat162float(h));
    }
}

// ================= HMMA split-bf16 GEMM (128x256 CTA, 64x64 warp tile) =================
#define G_STAGE 49152
#define G_SMEM  (3 * G_STAGE)

__device__ __forceinline__ void gemm_load_chunk(
    uint32_t stage, int tid,
    const __nv_bfloat16* Ahi, const __nv_bfloat16* Alo, int Astride,
    const __nv_bfloat16* Bhi, const __nv_bfloat16* Blo,
    int m0, int n0, int kc, int K)
{
#pragma unroll
    for (int i = 0; i < 12; i++) {
        int f = i * 256 + tid;
        const __nv_bfloat16* src;
        uint32_t dst;
        if (f < 1024) {                 // A: hi 512 units, lo 512 units (128 rows x 4)
            int t = f >> 9, r = (f >> 2) & 127, u = f & 3;
            src = ((t == 0) ? Ahi : Alo) + (size_t)(m0 + r) * Astride + kc + u * 8;
            dst = stage + t * 8192 + r * 64 + ((u ^ ((r >> 1) & 3)) * 16);
        } else {                        // B: hi 1024 units, lo 1024 units (256 rows x 4)
            int g = f - 1024;
            int t = g >> 10, r = (g >> 2) & 255, u = g & 3;
            src = ((t == 0) ? Bhi : Blo) + (size_t)(n0 + r) * K + kc + u * 8;
            dst = stage + 16384 + t * 16384 + r * 64 + ((u ^ ((r >> 1) & 3)) * 16);
        }
        cp16(dst, src);
    }
    asm volatile("cp.async.commit_group;" ::: "memory");
}

// mode 0: fp32 C.  mode 1: bf16 hi/lo split.  mode 2: L1 combined.  mode 3: L2 combined.
__global__ __launch_bounds__(256) void hmma_gemm_kernel(
    const __nv_bfloat16* __restrict__ Ahi, const __nv_bfloat16* __restrict__ Alo, int Astride,
    const __nv_bfloat16* __restrict__ Bhi, const __nv_bfloat16* __restrict__ Blo,
    float* __restrict__ C, __nv_bfloat16* __restrict__ Chi, __nv_bfloat16* __restrict__ Clo,
    float* __restrict__ C2,
    int mode, int N, int K, int Cstride)
{
    extern __shared__ __align__(128) char smem[];
    uint32_t sb = smem_u32(smem);
    const int tid = threadIdx.x, lane = tid & 31, wid = tid >> 5;
    const int wm = wid >> 2, wn = wid & 3;          // 2 x 4 warps, 64x64 tiles
    const int m0 = blockIdx.y << 7;
    const int q = lane >> 3, rr = lane & 7;

    const __nv_bfloat16 *pAh = Ahi, *pAl = Alo;
    const __nv_bfloat16 *pBh = Bhi, *pBl = Blo;
    float* pC = C;
    int cstr = Cstride;
    int n0;
    int emode = mode;
    if (mode == 3) {
        emode = 0;
        if (blockIdx.x < 12) {
            n0 = blockIdx.x << 8; cstr = 3072;
        } else {
            n0 = ((int)blockIdx.x - 12) << 8;
            pAh += 512; pAl += 512;
            pBh += L2Q_DELTA; pBl += L2Q_DELTA;
            pC = C2; cstr = 2048;
        }
    } else {
        n0 = blockIdx.x << 8;
    }

    uint32_t offA[4][2], offB[4][2];
#pragma unroll
    for (int mi = 0; mi < 4; mi++)
#pragma unroll
        for (int ks = 0; ks < 2; ks++) {
            int row = wm * 64 + mi * 16 + (q & 1) * 8 + rr;
            int u = ks * 2 + (q >> 1);
            offA[mi][ks] = row * 64 + ((u ^ ((row >> 1) & 3)) * 16);
        }
#pragma unroll
    for (int n2 = 0; n2 < 4; n2++)
#pragma unroll
        for (int ks = 0; ks < 2; ks++) {
            int row = wn * 64 + n2 * 16 + (q >> 1) * 8 + rr;
            int u = ks * 2 + (q & 1);
            offB[n2][ks] = row * 64 + ((u ^ ((row >> 1) & 3)) * 16);
        }

    float acc[4][8][4];
#pragma unroll
    for (int a = 0; a < 4; a++)
#pragma unroll
        for (int b = 0; b < 8; b++)
#pragma unroll
            for (int cc = 0; cc < 4; cc++) acc[a][b][cc] = 0.0f;

    const int NC = K >> 5;

    gemm_load_chunk(sb,           tid, pAh, pAl, Astride, pBh, pBl, m0, n0, 0,  K);
    gemm_load_chunk(sb + G_STAGE, tid, pAh, pAl, Astride, pBh, pBl, m0, n0, 32, K);

    int sidx = 0;
    for (int c = 0; c < NC; c++) {
        if (c + 1 < NC) asm volatile("cp.async.wait_group 1;" ::: "memory");
        else            asm volatile("cp.async.wait_group 0;" ::: "memory");
        __syncthreads();

        if (c + 2 < NC) {
            int s2 = sidx + 2; if (s2 >= 3) s2 -= 3;
            gemm_load_chunk(sb + s2 * G_STAGE, tid, pAh, pAl, Astride, pBh, pBl,
                            m0, n0, (c + 2) << 5, K);
        }

        const uint32_t stage = sb + sidx * G_STAGE;
#pragma unroll
        for (int ks = 0; ks < 2; ks++) {
            // term-phased: load sets as needed to cap live registers
            uint32_t ah[4][4], bh[4][4];
#pragma unroll
            for (int mi = 0; mi < 4; mi++) ldmx4(ah[mi], stage + offA[mi][ks]);
#pragma unroll
            for (int n2 = 0; n2 < 4; n2++) ldmx4(bh[n2], stage + 16384 + offB[n2][ks]);
            // term 1: ah x bh
#pragma unroll
            for (int mi = 0; mi < 4; mi++)
#pragma unroll
                for (int ni = 0; ni < 8; ni++)
                    mma16816(acc[mi][ni], ah[mi], bh[ni >> 1][(ni & 1) * 2], bh[ni >> 1][(ni & 1) * 2 + 1]);
            // term 2: ah x bl (bl overwrites nothing; loaded now)
            {
                uint32_t bl[4][4];
#pragma unroll
                for (int n2 = 0; n2 < 4; n2++) ldmx4(bl[n2], stage + 32768 + offB[n2][ks]);
#pragma unroll
                for (int mi = 0; mi < 4; mi++)
#pragma unroll
                    for (int ni = 0; ni < 8; ni++)
                        mma16816(acc[mi][ni], ah[mi], bl[ni >> 1][(ni & 1) * 2], bl[ni >> 1][(ni & 1) * 2 + 1]);
            }
            // term 3: al x bh (al loaded now, reuses bh)
            {
                uint32_t al[4][4];
#pragma unroll
                for (int mi = 0; mi < 4; mi++) ldmx4(al[mi], stage + 8192 + offA[mi][ks]);
#pragma unroll
                for (int mi = 0; mi < 4; mi++)
#pragma unroll
                    for (int ni = 0; ni < 8; ni++)
                        mma16816(acc[mi][ni], al[mi], bh[ni >> 1][(ni & 1) * 2], bh[ni >> 1][(ni & 1) * 2 + 1]);
            }
        }
        sidx++; if (sidx == 3) sidx = 0;
    }

    const int cm = m0 + wm * 64 + (lane >> 2);
    int cn = n0 + wn * 64 + (lane & 3) * 2;
    if (mode == 2) {
        if (n0 < 1024) { emode = 1; cstr = 1024; }
        else           { emode = 0; cstr = 1024; cn -= 1024; }
    }
    if (emode == 0) {
#pragma unroll
        for (int mi = 0; mi < 4; mi++) {
#pragma unroll
            for (int ni = 0; ni < 8; ni++) {
                float* p0 = pC + (size_t)(cm + mi * 16)     * cstr + cn + ni * 8;
                float* p1 = pC + (size_t)(cm + mi * 16 + 8) * cstr + cn + ni * 8;
                *(float2*)p0 = make_float2(acc[mi][ni][0], acc[mi][ni][1]);
                *(float2*)p1 = make_float2(acc[mi][ni][2], acc[mi][ni][3]);
            }
        }
    } else {
#pragma unroll
        for (int mi = 0; mi < 4; mi++) {
#pragma unroll
            for (int ni = 0; ni < 8; ni++) {
                uint32_t h0, l0, h1, l1;
                bsplit2(acc[mi][ni][0], acc[mi][ni][1], h0, l0);
                bsplit2(acc[mi][ni][2], acc[mi][ni][3], h1, l1);
                size_t o0 = (size_t)(cm + mi * 16)     * cstr + cn + ni * 8;
                size_t o1 = (size_t)(cm + mi * 16 + 8) * cstr + cn + ni * 8;
                *(uint32_t*)(Chi + o0) = h0; *(uint32_t*)(Clo + o0) = l0;
                *(uint32_t*)(Chi + o1) = h1; *(uint32_t*)(Clo + o1) = l1;
            }
        }
    }
}

// ---------------- merged Vt transpose-split + q/k assemble (RoPE) ----------------
__global__ __launch_bounds__(256) void vtasm_kernel(
    const float* __restrict__ V, int Vstride,
    __nv_bfloat16* __restrict__ Vh, __nv_bfloat16* __restrict__ Vl,
    const float* __restrict__ qout, const float* __restrict__ kvout,
    const float* __restrict__ krope,
    const float* __restrict__ cosT, const float* __restrict__ sinT,
    __nv_bfloat16* __restrict__ Qh, __nv_bfloat16* __restrict__ Ql,
    __nv_bfloat16* __restrict__ Kh, __nv_bfloat16* __restrict__ Kl)
{
    int tb = blockIdx.x;
    int tid = threadIdx.x;
    if (tb < 8192) {
        __shared__ float t[32][33];
        int s0  = (tb & 63) * 32;
        int d0  = ((tb >> 6) & 3) * 32;
        int bh_ = tb >> 8;
        int b = bh_ >> 4, h = bh_ & 15;
        int tx = tid & 31, ty = tid >> 5;
        for (int j = ty; j < 32; j += 8)
            t[j][tx] = V[(size_t)(b * S_LEN + s0 + j) * Vstride + h * HD + d0 + tx];
        __syncthreads();
        for (int j = ty; j < 32; j += 8) {
            float v = t[tx][j];
            __nv_bfloat16 hh = __float2bfloat16(v);
            size_t o = ((size_t)bh_ * HD + d0 + j) * S_LEN + s0 + tx;
            Vh[o] = hh;
            Vl[o] = __float2bfloat16(v - __bfloat162float(hh));
        }
        return;
    }

    const float scale = 0.08838834764831845f;   // 1/sqrt(128)
    int idx = (tb - 8192) * 256 + tid;
    int row = idx >> 10;
    int hj  = idx & 1023;
    int h = hj >> 6;
    int j = hj & 63;
    int s = row & (S_LEN - 1);

    size_t o0 = (size_t)row * HIDDEN + h * HD + j;
    size_t o1 = o0 + 64;

    float qn = qout[(size_t)row * 2048 + hj] * scale;
    float kn = kvout[(size_t)row * 3072 + hj];
    __nv_bfloat16 t;
    t = __float2bfloat16(qn); Qh[o0] = t; Ql[o0] = __float2bfloat16(qn - __bfloat162float(t));
    t = __float2bfloat16(kn); Kh[o0] = t; Kl[o0] = __float2bfloat16(kn - __bfloat162float(t));

    int fi = j & 31;
    float c  = cosT[s * 32 + fi];
    float sn = sinT[s * 32 + fi];
    int d = (j < 32) ? 32 : -32;
    float sgn = (j < 32) ? -1.0f : 1.0f;
    float qr0 = qout[(size_t)row * 2048 + 1024 + hj];
    float qr1 = qout[(size_t)row * 2048 + 1024 + hj + d];
    float kr0 = krope[(size_t)row * 1024 + hj];
    float kr1 = krope[(size_t)row * 1024 + hj + d];
    float qv = (qr0 * c + sgn * qr1 * sn) * scale;
    float kv =  kr0 * c + sgn * kr1 * sn;
    t = __float2bfloat16(qv); Qh[o1] = t; Ql[o1] = __float2bfloat16(qv - __bfloat162float(t));
    t = __float2bfloat16(kv); Kh[o1] = t; Kl[o1] = __float2bfloat16(kv - __bfloat162float(t));
}

// ================= HMMA flash attention =================
#define A_SMEM (32768 + 2 * 65536)

__device__ __forceinline__ void attn_load_tile(
    uint32_t stg, int tid, int b, int h, int k0,
    const __nv_bfloat16* Kh, const __nv_bfloat16* Kl,
    const __nv_bfloat16* Vh, const __nv_bfloat16* Vl)
{
#pragma unroll
    for (int i = 0; i < 32; i++) {
        int f = i * 128 + tid;
        int t = f >> 10;       // 0:Kh 1:Kl 2:Vh 3:Vl
        int g = f & 1023;
        if (t < 2) {
            int r = g >> 4, u = g & 15;
            const __nv_bfloat16* src = ((t == 0) ? Kh : Kl)
                + (size_t)(b * S_LEN + k0 + r) * HIDDEN + h * HD + u * 8;
            cp16(stg + t * 16384 + r * 256 + ((u ^ (r & 7)) << 4), src);
        } else {
            int d = g >> 3, u = g & 7;
            const __nv_bfloat16* src = ((t == 2) ? Vh : Vl)
                + ((size_t)(b * NH + h) * HD + d) * S_LEN + k0 + u * 8;
            cp16(stg + t * 16384 + d * 128 + ((u ^ (d & 7)) << 4), src);
        }
    }
    asm volatile("cp.async.commit_group;" ::: "memory");
}

__global__ __launch_bounds__(128) void fattn_kernel(
    const __nv_bfloat16* __restrict__ Qh, const __nv_bfloat16* __restrict__ Ql,
    const __nv_bfloat16* __restrict__ Kh, const __nv_bfloat16* __restrict__ Kl,
    const __nv_bfloat16* __restrict__ Vth, const __nv_bfloat16* __restrict__ Vtl,
    __nv_bfloat16* __restrict__ Yh, __nv_bfloat16* __restrict__ Yl)
{
    extern __shared__ __align__(128) char smem[];
    uint32_t sb = smem_u32(smem);
    const int qt = (S_LEN / 64 - 1) - blockIdx.x;   // long rows first
    const int h = blockIdx.y, b = blockIdx.z;
    const int tid = threadIdx.x, lane = tid & 31, wm = tid >> 5;
    const int q0 = qt * 64;
    const int rr = lane & 7, qq = lane >> 3;
    const int qb0 = qq >> 1, qb1 = qq & 1;

    // load Q tiles (hi+lo)
#pragma unroll
    for (int i = 0; i < 16; i++) {
        int f = i * 128 + tid;
        int t = f >> 10;
        int g = f & 1023;
        int r = g >> 4, u = g & 15;
        const __nv_bfloat16* src = ((t == 0) ? Qh : Ql)
            + (size_t)(b * S_LEN + q0 + r) * HIDDEN + h * HD + u * 8;
        cp16(sb + t * 16384 + r * 256 + ((u ^ (r & 7)) << 4), src);
    }
    asm volatile("cp.async.commit_group;" ::: "memory");

    attn_load_tile(sb + 32768,         tid, b, h, 0,  Kh, Kl, Vth, Vtl);
    if (qt >= 1) attn_load_tile(sb + 32768 + 65536, tid, b, h, 64, Kh, Kl, Vth, Vtl);

    float o[16][4];
#pragma unroll
    for (int j = 0; j < 16; j++)
#pragma unroll
        for (int e = 0; e < 4; e++) o[j][e] = 0.0f;
    float m0 = -1e30f, m1 = -1e30f, l0 = 0.0f, l1 = 0.0f;

    const int rA = wm * 16 + qb1 * 8 + rr;
    const uint32_t offQbase = rA * 256;
    const int swA = rA & 7;

    for (int kt = 0; kt <= qt; kt++) {
        if (kt < qt) asm volatile("cp.async.wait_group 1;" ::: "memory");
        else         asm volatile("cp.async.wait_group 0;" ::: "memory");
        __syncthreads();

        const uint32_t stg = sb + 32768 + (kt & 1) * 65536;
        const int k0 = kt * 64;

        // ---- S = Q K^T (3-term split; n2 pairs, term-major) ----
        float s[8][4];
#pragma unroll
        for (int j = 0; j < 8; j++)
#pragma unroll
            for (int e = 0; e < 4; e++) s[j][e] = 0.0f;

#pragma unroll
        for (int ks = 0; ks < 8; ks++) {
            uint32_t ah[4], al[4];
            uint32_t ua = 2 * ks + qb0;
            uint32_t qoff = offQbase + ((ua ^ swA) << 4);
            ldmx4(ah, sb + qoff);
            ldmx4(al, sb + 16384 + qoff);
#pragma unroll
            for (int np = 0; np < 2; np++) {
                uint32_t bh[2][4], bl[2][4];
#pragma unroll
                for (int i = 0; i < 2; i++) {
                    int rB = (np * 2 + i) * 16 + qb0 * 8 + rr;
                    uint32_t ub = 2 * ks + qb1;
                    uint32_t koff = rB * 256 + (((ub ^ (rB & 7))) << 4);
                    ldmx4(bh[i], stg + koff);
                    ldmx4(bl[i], stg + 16384 + koff);
                }
                float* s0 = s[4 * np];
                float* s1 = s[4 * np + 1];
                float* s2 = s[4 * np + 2];
                float* s3 = s[4 * np + 3];
                mma16816(s0, ah, bh[0][0], bh[0][1]);
                mma16816(s1, ah, bh[0][2], bh[0][3]);
                mma16816(s2, ah, bh[1][0], bh[1][1]);
                mma16816(s3, ah, bh[1][2], bh[1][3]);
                mma16816(s0, ah, bl[0][0], bl[0][1]);
                mma16816(s1, ah, bl[0][2], bl[0][3]);
                mma16816(s2, ah, bl[1][0], bl[1][1]);
                mma16816(s3, ah, bl[1][2], bl[1][3]);
                mma16816(s0, al, bh[0][0], bh[0][1]);
                mma16816(s1, al, bh[0][2], bh[0][3]);
                mma16816(s2, al, bh[1][0], bh[1][1]);
                mma16816(s3, al, bh[1][2], bh[1][3]);
            }
        }

        // ---- causal mask (diagonal tile only) ----
        if (kt == qt) {
            int rbase = q0 + wm * 16 + (lane >> 2);
            int cbase = k0 + (lane & 3) * 2;
#pragma unroll
            for (int j = 0; j < 8; j++) {
                int c0 = cbase + j * 8, c1 = c0 + 1;
                if (c0 > rbase)     s[j][0] = -1e30f;
                if (c1 > rbase)     s[j][1] = -1e30f;
                if (c0 > rbase + 8) s[j][2] = -1e30f;
                if (c1 > rbase + 8) s[j][3] = -1e30f;
            }
        }

        // ---- online softmax ----
        float mt0 = -1e30f, mt1 = -1e30f;
#pragma unroll
        for (int j = 0; j < 8; j++) {
            mt0 = fmaxf(mt0, fmaxf(s[j][0], s[j][1]));
            mt1 = fmaxf(mt1, fmaxf(s[j][2], s[j][3]));
        }
        mt0 = fmaxf(mt0, __shfl_xor_sync(0xffffffffu, mt0, 1));
        mt0 = fmaxf(mt0, __shfl_xor_sync(0xffffffffu, mt0, 2));
        mt1 = fmaxf(mt1, __shfl_xor_sync(0xffffffffu, mt1, 1));
        mt1 = fmaxf(mt1, __shfl_xor_sync(0xffffffffu, mt1, 2));
        float mn0 = fmaxf(m0, mt0), mn1 = fmaxf(m1, mt1);
        float cr0 = __expf(m0 - mn0), cr1 = __expf(m1 - mn1);
        m0 = mn0; m1 = mn1;

        float ps0 = 0.0f, ps1 = 0.0f;
#pragma unroll
        for (int j = 0; j < 8; j++) {
            s[j][0] = __expf(s[j][0] - mn0);
            s[j][1] = __expf(s[j][1] - mn0);
            s[j][2] = __expf(s[j][2] - mn1);
            s[j][3] = __expf(s[j][3] - mn1);
            ps0 += s[j][0] + s[j][1];
            ps1 += s[j][2] + s[j][3];
        }
        ps0 += __shfl_xor_sync(0xffffffffu, ps0, 1);
        ps0 += __shfl_xor_sync(0xffffffffu, ps0, 2);
        ps1 += __shfl_xor_sync(0xffffffffu, ps1, 1);
        ps1 += __shfl_xor_sync(0xffffffffu, ps1, 2);
        l0 = l0 * cr0 + ps0;
        l1 = l1 * cr1 + ps1;
#pragma unroll
        for (int j = 0; j < 16; j++) {
            o[j][0] *= cr0; o[j][1] *= cr0;
            o[j][2] *= cr1; o[j][3] *= cr1;
        }

        // ---- P -> bf16 hi/lo A-fragments ----
        uint32_t phi[4][4], plo[4][4];
#pragma unroll
        for (int ks = 0; ks < 4; ks++) {
            bsplit2(s[2 * ks][0],     s[2 * ks][1],     phi[ks][0], plo[ks][0]);
            bsplit2(s[2 * ks][2],     s[2 * ks][3],     phi[ks][1], plo[ks][1]);
            bsplit2(s[2 * ks + 1][0], s[2 * ks + 1][1], phi[ks][2], plo[ks][2]);
            bsplit2(s[2 * ks + 1][2], s[2 * ks + 1][3], phi[ks][3], plo[ks][3]);
        }

        // ---- O += P @ V (3-term split; ks-outer, v2 pairs, term-major) ----
#pragma unroll
        for (int ks = 0; ks < 4; ks++) {
            uint32_t u = 2 * ks + qb1;
#pragma unroll
            for (int vp = 0; vp < 4; vp++) {
                uint32_t bh[2][4], bl[2][4];
#pragma unroll
                for (int i = 0; i < 2; i++) {
                    int rv = (vp * 2 + i) * 16 + qb0 * 8 + rr;
                    uint32_t vbase = stg + 32768 + rv * 128;
                    uint32_t voff = (u ^ (rv & 7)) << 4;
                    ldmx4(bh[i], vbase + voff);
                    ldmx4(bl[i], vbase + 16384 + voff);
                }
                float* o0 = o[vp * 4];
                float* o1 = o[vp * 4 + 1];
                float* o2 = o[vp * 4 + 2];
                float* o3 = o[vp * 4 + 3];
                mma16816(o0, phi[ks], bh[0][0], bh[0][1]);
                mma16816(o1, phi[ks], bh[0][2], bh[0][3]);
                mma16816(o2, phi[ks], bh[1][0], bh[1][1]);
                mma16816(o3, phi[ks], bh[1][2], bh[1][3]);
                mma16816(o0, phi[ks], bl[0][0], bl[0][1]);
                mma16816(o1, phi[ks], bl[0][2], bl[0][3]);
                mma16816(o2, phi[ks], bl[1][0], bl[1][1]);
                mma16816(o3, phi[ks], bl[1][2], bl[1][3]);
                mma16816(o0, plo[ks], bh[0][0], bh[0][1]);
                mma16816(o1, plo[ks], bh[0][2], bh[0][3]);
                mma16816(o2, plo[ks], bh[1][0], bh[1][1]);
                mma16816(o3, plo[ks], bh[1][2], bh[1][3]);
            }
        }

        if (kt + 2 <= qt) {
            __syncthreads();
            attn_load_tile(sb + 32768 + (kt & 1) * 65536, tid, b, h, (kt + 2) * 64,
                           Kh, Kl, Vth, Vtl);
        }
    }

    // ---- epilogue: write bf16 hi/lo directly (Y pre-split) ----
    float inv0 = 1.0f / l0, inv1 = 1.0f / l1;
    int row0 = b * S_LEN + q0 + wm * 16 + (lane >> 2);
    int colb = h * HD + (lane & 3) * 2;
#pragma unroll
    for (int j = 0; j < 16; j++) {
        uint32_t hh, ll;
        size_t o0 = (size_t)row0 * HIDDEN + colb + j * 8;
        size_t o1 = (size_t)(row0 + 8) * HIDDEN + colb + j * 8;
        bsplit2(o[j][0] * inv0, o[j][1] * inv0, hh, ll);
        *(uint32_t*)(Yh + o0) = hh; *(uint32_t*)(Yl + o0) = ll;
        bsplit2(o[j][2] * inv1, o[j][3] * inv1, hh, ll);
        *(uint32_t*)(Yh + o1) = hh; *(uint32_t*)(Yl + o1) = ll;
    }
}

// ---------------- host ----------------
extern "C" void kernel_launch(void* const* d_in, const int* in_sizes, int n_in,
                              void* d_out, int out_size)
{
    const float* x        = (const float*)d_in[0];
    const float* W_kv_d   = (const float*)d_in[1];
    const float* W_q_d    = (const float*)d_in[2];
    const float* W_k_u    = (const float*)d_in[3];
    const float* W_q_u    = (const float*)d_in[4];
    const float* W_v_u    = (const float*)d_in[5];
    const float* W_rope_k = (const float*)d_in[6];
    const float* W_rope_q = (const float*)d_in[7];
    const float* W_o      = (const float*)d_in[8];
    float* out = (float*)d_out;

    float *k_rope, *kvout, *qout, *cosT, *sinT;
    __nv_bfloat16 *xbh, *xbl, *lath, *latl, *wbh, *wbl;
    __nv_bfloat16 *Qh, *Ql, *Kh, *Kl, *Vth, *Vtl;
    cudaGetSymbolAddress((void**)&k_rope, g_k_rope);
    cudaGetSymbolAddress((void**)&kvout,  g_kvout);
    cudaGetSymbolAddress((void**)&qout,   g_qout);
    cudaGetSymbolAddress((void**)&cosT,   g_cos);
    cudaGetSymbolAddress((void**)&sinT,   g_sin);
    cudaGetSymbolAddress((void**)&xbh,    g_xb_hi);
    cudaGetSymbolAddress((void**)&xbl,    g_xb_lo);
    cudaGetSymbolAddress((void**)&lath,   g_lat_hi);
    cudaGetSymbolAddress((void**)&latl,   g_lat_lo);
    cudaGetSymbolAddress((void**)&wbh,    g_wb_hi);
    cudaGetSymbolAddress((void**)&wbl,    g_wb_lo);
    cudaGetSymbolAddress((void**)&Qh,     g_Qh);
    cudaGetSymbolAddress((void**)&Ql,     g_Ql);
    cudaGetSymbolAddress((void**)&Kh,     g_Kh);
    cudaGetSymbolAddress((void**)&Kl,     g_Kl);
    cudaGetSymbolAddress((void**)&Vth,    g_Vth);
    cudaGetSymbolAddress((void**)&Vtl,    g_Vtl);

    cudaFuncSetAttribute(hmma_gemm_kernel, cudaFuncAttributeMaxDynamicSharedMemorySize, G_SMEM);
    cudaFuncSetAttribute(fattn_kernel, cudaFuncAttributeMaxDynamicSharedMemorySize, A_SMEM);

    // 1: weight conversions + RoPE table + x split (one launch)
    dim3 wb(32, 8);
    wconv_all_kernel<<<19200, wb>>>(W_kv_d, W_q_d, W_rope_k, W_k_u, W_v_u,
                                    W_q_u, W_rope_q, W_o, wbh, wbl, cosT, sinT,
                                    x, xbh, xbl);

    // 2: L1 combined GEMM (K=2048, N=2048): latents split + fp32 k_rope
    hmma_gemm_kernel<<<dim3(8, 32), 256, G_SMEM>>>(
        xbh, xbl, 2048, wbh + OFF_L1, wbl + OFF_L1,
        k_rope, lath, latl, nullptr, 2, 2048, 2048, 1024);

    // 3: L2 merged GEMM (K=512): bx<12 -> kvout (N=3072), bx>=12 -> qout (N=2048)
    hmma_gemm_kernel<<<dim3(20, 32), 256, G_SMEM>>>(
        lath, latl, 1024, wbh + OFF_L2KV, wbl + OFF_L2KV,
        kvout, nullptr, nullptr, qout, 3, 0, 512, 0);

    // 4: merged Vt transpose-split + q/k assemble
    vtasm_kernel<<<24576, 256>>>(kvout + 1024, 3072, Vth, Vtl,
                                 qout, kvout, k_rope, cosT, sinT, Qh, Ql, Kh, Kl);

    // 5: HMMA flash attention (writes Y pre-split into xbh/xbl)
    dim3 agrid(S_LEN / 64, NH, B_SZ);
    fattn_kernel<<<agrid, 128, A_SMEM>>>(Qh, Ql, Kh, Kl, Vth, Vtl, xbh, xbl);

    // 6: output projection
    hmma_gemm_kernel<<<dim3(8, 32), 256, G_SMEM>>>(
        xbh, xbl, 2048, wbh + OFF_O, wbl + OFF_O,
        out, nullptr, nullptr, nullptr, 0, 2048, 2048, 2048);
}

// round 15
// speedup vs baseline: 1.0838x; 1.0838x over previous
#include <cuda_runtime.h>
#include <cuda_bf16.h>
#include <cstdint>
#include <math.h>

#define S_LEN   2048
#define B_SZ    2
#define NH      16
#define HD      128
#define M_TOT   (B_SZ * S_LEN)     /* 4096 */
#define HIDDEN  2048
#define LATENT  512

// ---------------- scratch (device globals: no allocation allowed) ----------------
__device__ float g_k_rope[M_TOT * 1024];          // fp32 rope-k (pre-RoPE)
__device__ float g_kvout [M_TOT * 3072];          // cols 0-1023: k_half, 1024-3071: V
__device__ float g_qout  [M_TOT * 2048];          // cols 0-1023: q_half, 1024-2047: q_rope
__device__ float g_cos   [S_LEN * 32];
__device__ float g_sin   [S_LEN * 32];

// bf16 hi/lo split buffers
__device__ __nv_bfloat16 g_xb_hi[M_TOT * HIDDEN];   // x split; later reused for attention output Y
__device__ __nv_bfloat16 g_xb_lo[M_TOT * HIDDEN];
__device__ __nv_bfloat16 g_lat_hi[M_TOT * 1024];    // cols 0-511: kv latent, 512-1023: q latent
__device__ __nv_bfloat16 g_lat_lo[M_TOT * 1024];

// attention operands (bf16 hi/lo)
__device__ __nv_bfloat16 g_Qh[M_TOT * HIDDEN];
__device__ __nv_bfloat16 g_Ql[M_TOT * HIDDEN];
__device__ __nv_bfloat16 g_Kh[M_TOT * HIDDEN];
__device__ __nv_bfloat16 g_Kl[M_TOT * HIDDEN];
__device__ __nv_bfloat16 g_Vth[B_SZ * NH * HD * S_LEN];  // [b][h][d][s]
__device__ __nv_bfloat16 g_Vtl[B_SZ * NH * HD * S_LEN];

// packed transposed weights [N,K] bf16 hi/lo
#define OFF_L1     0
#define OFF_L2KV   4194304
#define OFF_L2Q    5767168
#define OFF_O      6815744
#define W_POOL     11010048
#define L2Q_DELTA  (OFF_L2Q - OFF_L2KV)   /* 1572864 */
__device__ __nv_bfloat16 g_wb_hi[W_POOL];
__device__ __nv_bfloat16 g_wb_lo[W_POOL];

// ================= helpers =================
__device__ __forceinline__ uint32_t smem_u32(const void* p) {
    uint32_t a;
    asm("{ .reg .u64 t; cvta.to.shared.u64 t, %1; cvt.u32.u64 %0, t; }" : "=r"(a) : "l"(p));
    return a;
}

__device__ __forceinline__ void ldmx4(uint32_t* r, uint32_t addr) {
    asm volatile("ldmatrix.sync.aligned.m8n8.x4.shared.b16 {%0,%1,%2,%3}, [%4];"
        : "=r"(r[0]), "=r"(r[1]), "=r"(r[2]), "=r"(r[3]) : "r"(addr));
}

__device__ __forceinline__ void mma16816(float* c, const uint32_t* a, uint32_t b0, uint32_t b1) {
    asm volatile(
        "mma.sync.aligned.m16n8k16.row.col.f32.bf16.bf16.f32 "
        "{%0,%1,%2,%3}, {%4,%5,%6,%7}, {%8,%9}, {%0,%1,%2,%3};"
        : "+f"(c[0]), "+f"(c[1]), "+f"(c[2]), "+f"(c[3])
        : "r"(a[0]), "r"(a[1]), "r"(a[2]), "r"(a[3]), "r"(b0), "r"(b1));
}

__device__ __forceinline__ void cp16(uint32_t dst, const void* src) {
    unsigned long long g = (unsigned long long)__cvta_generic_to_global(src);
    asm volatile("cp.async.cg.shared.global [%0], [%1], 16;" :: "r"(dst), "l"(g) : "memory");
}

__device__ __forceinline__ void bsplit2(float a, float b, uint32_t& hi, uint32_t& lo) {
    __nv_bfloat162 h, l;
    h.x = __float2bfloat16(a); l.x = __float2bfloat16(a - __bfloat162float(h.x));
    h.y = __float2bfloat16(b); l.y = __float2bfloat16(b - __bfloat162float(h.y));
    hi = *(uint32_t*)&h; lo = *(uint32_t*)&l;
}

// ================= mega conversion kernel =================
// blocks [0,10752): weight transpose+split.  [10752,11008): RoPE table.
// [11008,19200): x -> bf16 hi/lo split.
__global__ void wconv_all_kernel(
    const float* __restrict__ W_kv_d, const float* __restrict__ W_q_d,
    const float* __restrict__ W_rope_k, const float* __restrict__ W_k_u,
    const float* __restrict__ W_v_u, const float* __restrict__ W_q_u,
    const float* __restrict__ W_rope_q, const float* __restrict__ W_o,
    __nv_bfloat16* __restrict__ hi, __nv_bfloat16* __restrict__ lo,
    float* __restrict__ cosT, float* __restrict__ sinT,
    const float* __restrict__ x,
    __nv_bfloat16* __restrict__ xhi, __nv_bfloat16* __restrict__ xlo)
{
    int tb = blockIdx.x;
    int tid = threadIdx.y * 32 + threadIdx.x;
    if (tb >= 11008) {   // x split: 8192 blocks x 256 threads x float4
        int i = (tb - 11008) * 256 + tid;
        float4 v = ((const float4*)x)[i];
        __nv_bfloat162 h01, h23, l01, l23;
        h01.x = __float2bfloat16(v.x); l01.x = __float2bfloat16(v.x - __bfloat162float(h01.x));
        h01.y = __float2bfloat16(v.y); l01.y = __float2bfloat16(v.y - __bfloat162float(h01.y));
        h23.x = __float2bfloat16(v.z); l23.x = __float2bfloat16(v.z - __bfloat162float(h23.x));
        h23.y = __float2bfloat16(v.w); l23.y = __float2bfloat16(v.w - __bfloat162float(h23.y));
        uint2 hv, lv;
        hv.x = *(uint32_t*)&h01; hv.y = *(uint32_t*)&h23;
        lv.x = *(uint32_t*)&l01; lv.y = *(uint32_t*)&l23;
        ((uint2*)xhi)[i] = hv;
        ((uint2*)xlo)[i] = lv;
        return;
    }
    if (tb >= 10752) {   // RoPE table: 256 blocks x 256 threads = 65536
        int idx = (tb - 10752) * 256 + tid;
        int s = idx >> 5;
        int i = idx & 31;
        double inv = exp(-((double)i / 32.0) * log(10000.0));
        double a   = (double)s * inv;
        cosT[idx] = (float)cos(a);
        sinT[idx] = (float)sin(a);
        return;
    }
    __shared__ float t[32][33];
    const float* W; int K, N; size_t off;
    if      (tb <  1024) { W = W_kv_d;   K = 2048; N =  512; off = OFF_L1;                    }
    else if (tb <  2048) { W = W_q_d;    K = 2048; N =  512; off = OFF_L1 + 1048576;  tb -= 1024; }
    else if (tb <  4096) { W = W_rope_k; K = 2048; N = 1024; off = OFF_L1 + 2097152;  tb -= 2048; }
    else if (tb <  4608) { W = W_k_u;    K =  512; N = 1024; off = OFF_L2KV;          tb -= 4096; }
    else if (tb <  5632) { W = W_v_u;    K =  512; N = 2048; off = OFF_L2KV + 524288; tb -= 4608; }
    else if (tb <  6144) { W = W_q_u;    K =  512; N = 1024; off = OFF_L2Q;           tb -= 5632; }
    else if (tb <  6656) { W = W_rope_q; K =  512; N = 1024; off = OFF_L2Q + 524288;  tb -= 6144; }
    else                 { W = W_o;      K = 2048; N = 2048; off = OFF_O;             tb -= 6656; }
    int ntn = N >> 5;
    int n0 = (tb % ntn) << 5, k0 = (tb / ntn) << 5;
    int tx = threadIdx.x, ty = threadIdx.y;
    for (int j = ty; j < 32; j += 8)
        t[j][tx] = W[(size_t)(k0 + j) * N + n0 + tx];
    __syncthreads();
    for (int j = ty; j < 32; j += 8) {
        float v = t[tx][j];
        __nv_bfloat16 h = __float2bfloat16(v);
        size_t o = off + (size_t)(n0 + j) * K + k0 + tx;
        hi[o] = h;
        lo[o] = __float2bfloat16(v - __bfloat162float(h));
    }
}

// ================= HMMA split-bf16 GEMM (R13-proven: 128x128 CTA, 64x32 warp) ==========
#define G_STAGE 32768
#define G_SMEM  (3 * G_STAGE)

__device__ __forceinline__ void gemm_load_chunk(
    uint32_t stage, int tid,
    const __nv_bfloat16* Ahi, const __nv_bfloat16* Alo, int Astride,
    const __nv_bfloat16* Bhi, const __nv_bfloat16* Blo,
    int m0, int n0, int kc, int K)
{
#pragma unroll
    for (int i = 0; i < 8; i++) {
        int f = i * 256 + tid;
        int t = f >> 9;
        int r = (f >> 2) & 127;
        int u = f & 3;
        const __nv_bfloat16* src;
        if (t < 2) src = ((t == 0) ? Ahi : Alo) + (size_t)(m0 + r) * Astride + kc + u * 8;
        else       src = ((t == 2) ? Bhi : Blo) + (size_t)(n0 + r) * K       + kc + u * 8;
        uint32_t dst = stage + t * 8192 + r * 64 + ((u ^ ((r >> 1) & 3)) * 16);
        cp16(dst, src);
    }
    asm volatile("cp.async.commit_group;" ::: "memory");
}

// mode 0: fp32 C.  mode 1: bf16 hi/lo split.  mode 2: L1 combined.  mode 3: L2 combined.
__global__ __launch_bounds__(256, 2) void hmma_gemm_kernel(
    const __nv_bfloat16* __restrict__ Ahi, const __nv_bfloat16* __restrict__ Alo, int Astride,
    const __nv_bfloat16* __restrict__ Bhi, const __nv_bfloat16* __restrict__ Blo,
    float* __restrict__ C, __nv_bfloat16* __restrict__ Chi, __nv_bfloat16* __restrict__ Clo,
    float* __restrict__ C2,
    int mode, int N, int K, int Cstride)
{
    extern __shared__ __align__(128) char smem[];
    uint32_t sb = smem_u32(smem);
    const int tid = threadIdx.x, lane = tid & 31, wid = tid >> 5;
    const int wm = wid >> 2, wn = wid & 3;
    const int m0 = blockIdx.y << 7;
    const int q = lane >> 3, rr = lane & 7;

    const __nv_bfloat16 *pAh = Ahi, *pAl = Alo;
    const __nv_bfloat16 *pBh = Bhi, *pBl = Blo;
    float* pC = C;
    int cstr = Cstride;
    int n0;
    int emode = mode;
    if (mode == 3) {
        emode = 0;
        if (blockIdx.x < 24) {
            n0 = blockIdx.x << 7; cstr = 3072;
        } else {
            n0 = ((int)blockIdx.x - 24) << 7;
            pAh += 512; pAl += 512;
            pBh += L2Q_DELTA; pBl += L2Q_DELTA;
            pC = C2; cstr = 2048;
        }
    } else {
        n0 = blockIdx.x << 7;
    }

    uint32_t offA[4][2], offB[2][2];
#pragma unroll
    for (int mi = 0; mi < 4; mi++)
#pragma unroll
        for (int ks = 0; ks < 2; ks++) {
            int row = wm * 64 + mi * 16 + (q & 1) * 8 + rr;
            int u = ks * 2 + (q >> 1);
            offA[mi][ks] = row * 64 + ((u ^ ((row >> 1) & 3)) * 16);
        }
#pragma unroll
    for (int n2 = 0; n2 < 2; n2++)
#pragma unroll
        for (int ks = 0; ks < 2; ks++) {
            int row = wn * 32 + n2 * 16 + (q >> 1) * 8 + rr;
            int u = ks * 2 + (q & 1);
            offB[n2][ks] = row * 64 + ((u ^ ((row >> 1) & 3)) * 16);
        }

    float acc[4][4][4];
#pragma unroll
    for (int a = 0; a < 4; a++)
#pragma unroll
        for (int b = 0; b < 4; b++)
#pragma unroll
            for (int cc = 0; cc < 4; cc++) acc[a][b][cc] = 0.0f;

    const int NC = K >> 5;

    gemm_load_chunk(sb,           tid, pAh, pAl, Astride, pBh, pBl, m0, n0, 0,  K);
    gemm_load_chunk(sb + G_STAGE, tid, pAh, pAl, Astride, pBh, pBl, m0, n0, 32, K);

    int sidx = 0;
    for (int c = 0; c < NC; c++) {
        if (c + 1 < NC) asm volatile("cp.async.wait_group 1;" ::: "memory");
        else            asm volatile("cp.async.wait_group 0;" ::: "memory");
        __syncthreads();

        if (c + 2 < NC) {
            int s2 = sidx + 2; if (s2 >= 3) s2 -= 3;
            gemm_load_chunk(sb + s2 * G_STAGE, tid, pAh, pAl, Astride, pBh, pBl,
                            m0, n0, (c + 2) << 5, K);
        }

        const uint32_t stage = sb + sidx * G_STAGE;
#pragma unroll
        for (int ks = 0; ks < 2; ks++) {
            uint32_t ah[4][4], al[4][4], bh[2][4], bl[2][4];
#pragma unroll
            for (int mi = 0; mi < 4; mi++) ldmx4(ah[mi], stage + offA[mi][ks]);
#pragma unroll
            for (int mi = 0; mi < 4; mi++) ldmx4(al[mi], stage + 8192 + offA[mi][ks]);
#pragma unroll
            for (int n2 = 0; n2 < 2; n2++) ldmx4(bh[n2], stage + 16384 + offB[n2][ks]);
#pragma unroll
            for (int n2 = 0; n2 < 2; n2++) ldmx4(bl[n2], stage + 24576 + offB[n2][ks]);
#pragma unroll
            for (int mi = 0; mi < 4; mi++)
#pragma unroll
                for (int ni = 0; ni < 4; ni++)
                    mma16816(acc[mi][ni], ah[mi], bh[ni >> 1][(ni & 1) * 2], bh[ni >> 1][(ni & 1) * 2 + 1]);
#pragma unroll
            for (int mi = 0; mi < 4; mi++)
#pragma unroll
                for (int ni = 0; ni < 4; ni++)
                    mma16816(acc[mi][ni], ah[mi], bl[ni >> 1][(ni & 1) * 2], bl[ni >> 1][(ni & 1) * 2 + 1]);
#pragma unroll
            for (int mi = 0; mi < 4; mi++)
#pragma unroll
                for (int ni = 0; ni < 4; ni++)
                    mma16816(acc[mi][ni], al[mi], bh[ni >> 1][(ni & 1) * 2], bh[ni >> 1][(ni & 1) * 2 + 1]);
        }
        sidx++; if (sidx == 3) sidx = 0;
    }

    const int cm = m0 + wm * 64 + (lane >> 2);
    int cn = n0 + wn * 32 + (lane & 3) * 2;
    if (mode == 2) {
        if (n0 < 1024) { emode = 1; cstr = 1024; }
        else           { emode = 0; cstr = 1024; cn -= 1024; }
    }
    if (emode == 0) {
#pragma unroll
        for (int mi = 0; mi < 4; mi++) {
#pragma unroll
            for (int ni = 0; ni < 4; ni++) {
                float* p0 = pC + (size_t)(cm + mi * 16)     * cstr + cn + ni * 8;
                float* p1 = pC + (size_t)(cm + mi * 16 + 8) * cstr + cn + ni * 8;
                *(float2*)p0 = make_float2(acc[mi][ni][0], acc[mi][ni][1]);
                *(float2*)p1 = make_float2(acc[mi][ni][2], acc[mi][ni][3]);
            }
        }
    } else {
#pragma unroll
        for (int mi = 0; mi < 4; mi++) {
#pragma unroll
            for (int ni = 0; ni < 4; ni++) {
                uint32_t h0, l0, h1, l1;
                bsplit2(acc[mi][ni][0], acc[mi][ni][1], h0, l0);
                bsplit2(acc[mi][ni][2], acc[mi][ni][3], h1, l1);
                size_t o0 = (size_t)(cm + mi * 16)     * cstr + cn + ni * 8;
                size_t o1 = (size_t)(cm + mi * 16 + 8) * cstr + cn + ni * 8;
                *(uint32_t*)(Chi + o0) = h0; *(uint32_t*)(Clo + o0) = l0;
                *(uint32_t*)(Chi + o1) = h1; *(uint32_t*)(Clo + o1) = l1;
            }
        }
    }
}

// ---------------- merged Vt transpose-split + q/k assemble (RoPE) ----------------
__global__ __launch_bounds__(256) void vtasm_kernel(
    const float* __restrict__ V, int Vstride,
    __nv_bfloat16* __restrict__ Vh, __nv_bfloat16* __restrict__ Vl,
    const float* __restrict__ qout, const float* __restrict__ kvout,
    const float* __restrict__ krope,
    const float* __restrict__ cosT, const float* __restrict__ sinT,
    __nv_bfloat16* __restrict__ Qh, __nv_bfloat16* __restrict__ Ql,
    __nv_bfloat16* __restrict__ Kh, __nv_bfloat16* __restrict__ Kl)
{
    int tb = blockIdx.x;
    int tid = threadIdx.x;
    if (tb < 8192) {
        __shared__ float t[32][33];
        int s0  = (tb & 63) * 32;
        int d0  = ((tb >> 6) & 3) * 32;
        int bh_ = tb >> 8;
        int b = bh_ >> 4, h = bh_ & 15;
        int tx = tid & 31, ty = tid >> 5;
        for (int j = ty; j < 32; j += 8)
            t[j][tx] = V[(size_t)(b * S_LEN + s0 + j) * Vstride + h * HD + d0 + tx];
        __syncthreads();
        for (int j = ty; j < 32; j += 8) {
            float v = t[tx][j];
            __nv_bfloat16 hh = __float2bfloat16(v);
            size_t o = ((size_t)bh_ * HD + d0 + j) * S_LEN + s0 + tx;
            Vh[o] = hh;
            Vl[o] = __float2bfloat16(v - __bfloat162float(hh));
        }
        return;
    }

    const float scale = 0.08838834764831845f;   // 1/sqrt(128)
    int idx = (tb - 8192) * 256 + tid;
    int row = idx >> 10;
    int hj  = idx & 1023;
    int h = hj >> 6;
    int j = hj & 63;
    int s = row & (S_LEN - 1);

    size_t o0 = (size_t)row * HIDDEN + h * HD + j;
    size_t o1 = o0 + 64;

    float qn = qout[(size_t)row * 2048 + hj] * scale;
    float kn = kvout[(size_t)row * 3072 + hj];
    __nv_bfloat16 t;
    t = __float2bfloat16(qn); Qh[o0] = t; Ql[o0] = __float2bfloat16(qn - __bfloat162float(t));
    t = __float2bfloat16(kn); Kh[o0] = t; Kl[o0] = __float2bfloat16(kn - __bfloat162float(t));

    int fi = j & 31;
    float c  = cosT[s * 32 + fi];
    float sn = sinT[s * 32 + fi];
    int d = (j < 32) ? 32 : -32;
    float sgn = (j < 32) ? -1.0f : 1.0f;
    float qr0 = qout[(size_t)row * 2048 + 1024 + hj];
    float qr1 = qout[(size_t)row * 2048 + 1024 + hj + d];
    float kr0 = krope[(size_t)row * 1024 + hj];
    float kr1 = krope[(size_t)row * 1024 + hj + d];
    float qv = (qr0 * c + sgn * qr1 * sn) * scale;
    float kv =  kr0 * c + sgn * kr1 * sn;
    t = __float2bfloat16(qv); Qh[o1] = t; Ql[o1] = __float2bfloat16(qv - __bfloat162float(t));
    t = __float2bfloat16(kv); Kh[o1] = t; Kl[o1] = __float2bfloat16(kv - __bfloat162float(t));
}

// ================= HMMA flash attention (single-buffer K/V, 2 CTAs/SM) =================
// Smem: Qhi|Qlo (16KB each) + ONE stage (Khi|Klo|Vthi|Vtlo 16KB each) = 96KB -> 2 CTAs/SM.
#define A_SMEM (32768 + 65536)

__device__ __forceinline__ void attn_load_tile(
    uint32_t stg, int tid, int b, int h, int k0,
    const __nv_bfloat16* Kh, const __nv_bfloat16* Kl,
    const __nv_bfloat16* Vh, const __nv_bfloat16* Vl)
{
#pragma unroll
    for (int i = 0; i < 32; i++) {
        int f = i * 128 + tid;
        int t = f >> 10;       // 0:Kh 1:Kl 2:Vh 3:Vl
        int g = f & 1023;
        if (t < 2) {
            int r = g >> 4, u = g & 15;
            const __nv_bfloat16* src = ((t == 0) ? Kh : Kl)
                + (size_t)(b * S_LEN + k0 + r) * HIDDEN + h * HD + u * 8;
            cp16(stg + t * 16384 + r * 256 + ((u ^ (r & 7)) << 4), src);
        } else {
            int d = g >> 3, u = g & 7;
            const __nv_bfloat16* src = ((t == 2) ? Vh : Vl)
                + ((size_t)(b * NH + h) * HD + d) * S_LEN + k0 + u * 8;
            cp16(stg + t * 16384 + d * 128 + ((u ^ (d & 7)) << 4), src);
        }
    }
    asm volatile("cp.async.commit_group;" ::: "memory");
}

__global__ __launch_bounds__(128, 2) void fattn_kernel(
    const __nv_bfloat16* __restrict__ Qh, const __nv_bfloat16* __restrict__ Ql,
    const __nv_bfloat16* __restrict__ Kh, const __nv_bfloat16* __restrict__ Kl,
    const __nv_bfloat16* __restrict__ Vth, const __nv_bfloat16* __restrict__ Vtl,
    __nv_bfloat16* __restrict__ Yh, __nv_bfloat16* __restrict__ Yl)
{
    extern __shared__ __align__(128) char smem[];
    uint32_t sb = smem_u32(smem);
    const int qt = (S_LEN / 64 - 1) - blockIdx.x;   // long rows first
    const int h = blockIdx.y, b = blockIdx.z;
    const int tid = threadIdx.x, lane = tid & 31, wm = tid >> 5;
    const int q0 = qt * 64;
    const int rr = lane & 7, qq = lane >> 3;
    const int qb0 = qq >> 1, qb1 = qq & 1;
    const uint32_t stg = sb + 32768;   // single K/V stage

    // load Q tiles (hi+lo)
#pragma unroll
    for (int i = 0; i < 16; i++) {
        int f = i * 128 + tid;
        int t = f >> 10;
        int g = f & 1023;
        int r = g >> 4, u = g & 15;
        const __nv_bfloat16* src = ((t == 0) ? Qh : Ql)
            + (size_t)(b * S_LEN + q0 + r) * HIDDEN + h * HD + u * 8;
        cp16(sb + t * 16384 + r * 256 + ((u ^ (r & 7)) << 4), src);
    }
    asm volatile("cp.async.commit_group;" ::: "memory");

    float o[16][4];
#pragma unroll
    for (int j = 0; j < 16; j++)
#pragma unroll
        for (int e = 0; e < 4; e++) o[j][e] = 0.0f;
    float m0 = -1e30f, m1 = -1e30f, l0 = 0.0f, l1 = 0.0f;

    const int rA = wm * 16 + qb1 * 8 + rr;
    const uint32_t offQbase = rA * 256;
    const int swA = rA & 7;

    for (int kt = 0; kt <= qt; kt++) {
        const int k0 = kt * 64;
        attn_load_tile(stg, tid, b, h, k0, Kh, Kl, Vth, Vtl);
        asm volatile("cp.async.wait_group 0;" ::: "memory");
        __syncthreads();

        // ---- S = Q K^T (3-term split; n2 pairs, term-major) ----
        float s[8][4];
#pragma unroll
        for (int j = 0; j < 8; j++)
#pragma unroll
            for (int e = 0; e < 4; e++) s[j][e] = 0.0f;

#pragma unroll
        for (int ks = 0; ks < 8; ks++) {
            uint32_t ah[4], al[4];
            uint32_t ua = 2 * ks + qb0;
            uint32_t qoff = offQbase + ((ua ^ swA) << 4);
            ldmx4(ah, sb + qoff);
            ldmx4(al, sb + 16384 + qoff);
#pragma unroll
            for (int np = 0; np < 2; np++) {
                uint32_t bh[2][4], bl[2][4];
#pragma unroll
                for (int i = 0; i < 2; i++) {
                    int rB = (np * 2 + i) * 16 + qb0 * 8 + rr;
                    uint32_t ub = 2 * ks + qb1;
                    uint32_t koff = rB * 256 + (((ub ^ (rB & 7))) << 4);
                    ldmx4(bh[i], stg + koff);
                    ldmx4(bl[i], stg + 16384 + koff);
                }
                float* s0 = s[4 * np];
                float* s1 = s[4 * np + 1];
                float* s2 = s[4 * np + 2];
                float* s3 = s[4 * np + 3];
                mma16816(s0, ah, bh[0][0], bh[0][1]);
                mma16816(s1, ah, bh[0][2], bh[0][3]);
                mma16816(s2, ah, bh[1][0], bh[1][1]);
                mma16816(s3, ah, bh[1][2], bh[1][3]);
                mma16816(s0, ah, bl[0][0], bl[0][1]);
                mma16816(s1, ah, bl[0][2], bl[0][3]);
                mma16816(s2, ah, bl[1][0], bl[1][1]);
                mma16816(s3, ah, bl[1][2], bl[1][3]);
                mma16816(s0, al, bh[0][0], bh[0][1]);
                mma16816(s1, al, bh[0][2], bh[0][3]);
                mma16816(s2, al, bh[1][0], bh[1][1]);
                mma16816(s3, al, bh[1][2], bh[1][3]);
            }
        }

        // ---- causal mask (diagonal tile only) ----
        if (kt == qt) {
            int rbase = q0 + wm * 16 + (lane >> 2);
            int cbase = k0 + (lane & 3) * 2;
#pragma unroll
            for (int j = 0; j < 8; j++) {
                int c0 = cbase + j * 8, c1 = c0 + 1;
                if (c0 > rbase)     s[j][0] = -1e30f;
                if (c1 > rbase)     s[j][1] = -1e30f;
                if (c0 > rbase + 8) s[j][2] = -1e30f;
                if (c1 > rbase + 8) s[j][3] = -1e30f;
            }
        }

        // ---- online softmax ----
        float mt0 = -1e30f, mt1 = -1e30f;
#pragma unroll
        for (int j = 0; j < 8; j++) {
            mt0 = fmaxf(mt0, fmaxf(s[j][0], s[j][1]));
            mt1 = fmaxf(mt1, fmaxf(s[j][2], s[j][3]));
        }
        mt0 = fmaxf(mt0, __shfl_xor_sync(0xffffffffu, mt0, 1));
        mt0 = fmaxf(mt0, __shfl_xor_sync(0xffffffffu, mt0, 2));
        mt1 = fmaxf(mt1, __shfl_xor_sync(0xffffffffu, mt1, 1));
        mt1 = fmaxf(mt1, __shfl_xor_sync(0xffffffffu, mt1, 2));
        float mn0 = fmaxf(m0, mt0), mn1 = fmaxf(m1, mt1);
        float cr0 = __expf(m0 - mn0), cr1 = __expf(m1 - mn1);
        m0 = mn0; m1 = mn1;

        float ps0 = 0.0f, ps1 = 0.0f;
#pragma unroll
        for (int j = 0; j < 8; j++) {
            s[j][0] = __expf(s[j][0] - mn0);
            s[j][1] = __expf(s[j][1] - mn0);
            s[j][2] = __expf(s[j][2] - mn1);
            s[j][3] = __expf(s[j][3] - mn1);
            ps0 += s[j][0] + s[j][1];
            ps1 += s[j][2] + s[j][3];
        }
        ps0 += __shfl_xor_sync(0xffffffffu, ps0, 1);
        ps0 += __shfl_xor_sync(0xffffffffu, ps0, 2);
        ps1 += __shfl_xor_sync(0xffffffffu, ps1, 1);
        ps1 += __shfl_xor_sync(0xffffffffu, ps1, 2);
        l0 = l0 * cr0 + ps0;
        l1 = l1 * cr1 + ps1;
#pragma unroll
        for (int j = 0; j < 16; j++) {
            o[j][0] *= cr0; o[j][1] *= cr0;
            o[j][2] *= cr1; o[j][3] *= cr1;
        }

        // ---- P -> bf16 hi/lo A-fragments ----
        uint32_t phi[4][4], plo[4][4];
#pragma unroll
        for (int ks = 0; ks < 4; ks++) {
            bsplit2(s[2 * ks][0],     s[2 * ks][1],     phi[ks][0], plo[ks][0]);
            bsplit2(s[2 * ks][2],     s[2 * ks][3],     phi[ks][1], plo[ks][1]);
            bsplit2(s[2 * ks + 1][0], s[2 * ks + 1][1], phi[ks][2], plo[ks][2]);
            bsplit2(s[2 * ks + 1][2], s[2 * ks + 1][3], phi[ks][3], plo[ks][3]);
        }

        // ---- O += P @ V (3-term split; ks-outer, v2 pairs, term-major) ----
#pragma unroll
        for (int ks = 0; ks < 4; ks++) {
            uint32_t u = 2 * ks + qb1;
#pragma unroll
            for (int vp = 0; vp < 4; vp++) {
                uint32_t bh[2][4], bl[2][4];
#pragma unroll
                for (int i = 0; i < 2; i++) {
                    int rv = (vp * 2 + i) * 16 + qb0 * 8 + rr;
                    uint32_t vbase = stg + 32768 + rv * 128;
                    uint32_t voff = (u ^ (rv & 7)) << 4;
                    ldmx4(bh[i], vbase + voff);
                    ldmx4(bl[i], vbase + 16384 + voff);
                }
                float* o0 = o[vp * 4];
                float* o1 = o[vp * 4 + 1];
                float* o2 = o[vp * 4 + 2];
                float* o3 = o[vp * 4 + 3];
                mma16816(o0, phi[ks], bh[0][0], bh[0][1]);
                mma16816(o1, phi[ks], bh[0][2], bh[0][3]);
                mma16816(o2, phi[ks], bh[1][0], bh[1][1]);
                mma16816(o3, phi[ks], bh[1][2], bh[1][3]);
                mma16816(o0, phi[ks], bl[0][0], bl[0][1]);
                mma16816(o1, phi[ks], bl[0][2], bl[0][3]);
                mma16816(o2, phi[ks], bl[1][0], bl[1][1]);
                mma16816(o3, phi[ks], bl[1][2], bl[1][3]);
                mma16816(o0, plo[ks], bh[0][0], bh[0][1]);
                mma16816(o1, plo[ks], bh[0][2], bh[0][3]);
                mma16816(o2, plo[ks], bh[1][0], bh[1][1]);
                mma16816(o3, plo[ks], bh[1][2], bh[1][3]);
            }
        }

        __syncthreads();   // all reads done before next tile overwrites the stage
    }

    // ---- epilogue: write bf16 hi/lo directly (Y pre-split) ----
    float inv0 = 1.0f / l0, inv1 = 1.0f / l1;
    int row0 = b * S_LEN + q0 + wm * 16 + (lane >> 2);
    int colb = h * HD + (lane & 3) * 2;
#pragma unroll
    for (int j = 0; j < 16; j++) {
        uint32_t hh, ll;
        size_t o0 = (size_t)row0 * HIDDEN + colb + j * 8;
        size_t o1 = (size_t)(row0 + 8) * HIDDEN + colb + j * 8;
        bsplit2(o[j][0] * inv0, o[j][1] * inv0, hh, ll);
        *(uint32_t*)(Yh + o0) = hh; *(uint32_t*)(Yl + o0) = ll;
        bsplit2(o[j][2] * inv1, o[j][3] * inv1, hh, ll);
        *(uint32_t*)(Yh + o1) = hh; *(uint32_t*)(Yl + o1) = ll;
    }
}

// ---------------- host ----------------
extern "C" void kernel_launch(void* const* d_in, const int* in_sizes, int n_in,
                              void* d_out, int out_size)
{
    const float* x        = (const float*)d_in[0];
    const float* W_kv_d   = (const float*)d_in[1];
    const float* W_q_d    = (const float*)d_in[2];
    const float* W_k_u    = (const float*)d_in[3];
    const float* W_q_u    = (const float*)d_in[4];
    const float* W_v_u    = (const float*)d_in[5];
    const float* W_rope_k = (const float*)d_in[6];
    const float* W_rope_q = (const float*)d_in[7];
    const float* W_o      = (const float*)d_in[8];
    float* out = (float*)d_out;

    float *k_rope, *kvout, *qout, *cosT, *sinT;
    __nv_bfloat16 *xbh, *xbl, *lath, *latl, *wbh, *wbl;
    __nv_bfloat16 *Qh, *Ql, *Kh, *Kl, *Vth, *Vtl;
    cudaGetSymbolAddress((void**)&k_rope, g_k_rope);
    cudaGetSymbolAddress((void**)&kvout,  g_kvout);
    cudaGetSymbolAddress((void**)&qout,   g_qout);
    cudaGetSymbolAddress((void**)&cosT,   g_cos);
    cudaGetSymbolAddress((void**)&sinT,   g_sin);
    cudaGetSymbolAddress((void**)&xbh,    g_xb_hi);
    cudaGetSymbolAddress((void**)&xbl,    g_xb_lo);
    cudaGetSymbolAddress((void**)&lath,   g_lat_hi);
    cudaGetSymbolAddress((void**)&latl,   g_lat_lo);
    cudaGetSymbolAddress((void**)&wbh,    g_wb_hi);
    cudaGetSymbolAddress((void**)&wbl,    g_wb_lo);
    cudaGetSymbolAddress((void**)&Qh,     g_Qh);
    cudaGetSymbolAddress((void**)&Ql,     g_Ql);
    cudaGetSymbolAddress((void**)&Kh,     g_Kh);
    cudaGetSymbolAddress((void**)&Kl,     g_Kl);
    cudaGetSymbolAddress((void**)&Vth,    g_Vth);
    cudaGetSymbolAddress((void**)&Vtl,    g_Vtl);

    cudaFuncSetAttribute(hmma_gemm_kernel, cudaFuncAttributeMaxDynamicSharedMemorySize, G_SMEM);
    cudaFuncSetAttribute(fattn_kernel, cudaFuncAttributeMaxDynamicSharedMemorySize, A_SMEM);

    // 1: weight conversions + RoPE table + x split (one launch)
    dim3 wb(32, 8);
    wconv_all_kernel<<<19200, wb>>>(W_kv_d, W_q_d, W_rope_k, W_k_u, W_v_u,
                                    W_q_u, W_rope_q, W_o, wbh, wbl, cosT, sinT,
                                    x, xbh, xbl);

    // 2: L1 combined GEMM (K=2048, N=2048): latents split + fp32 k_rope
    hmma_gemm_kernel<<<dim3(16, 32), 256, G_SMEM>>>(
        xbh, xbl, 2048, wbh + OFF_L1, wbl + OFF_L1,
        k_rope, lath, latl, nullptr, 2, 2048, 2048, 1024);

    // 3: L2 merged GEMM (K=512): bx<24 -> kvout (N=3072), bx>=24 -> qout (N=2048)
    hmma_gemm_kernel<<<dim3(40, 32), 256, G_SMEM>>>(
        lath, latl, 1024, wbh + OFF_L2KV, wbl + OFF_L2KV,
        kvout, nullptr, nullptr, qout, 3, 0, 512, 0);

    // 4: merged Vt transpose-split + q/k assemble
    vtasm_kernel<<<24576, 256>>>(kvout + 1024, 3072, Vth, Vtl,
                                 qout, kvout, k_rope, cosT, sinT, Qh, Ql, Kh, Kl);

    // 5: HMMA flash attention (single-buffer, 2 CTAs/SM; writes Y pre-split)
    dim3 agrid(S_LEN / 64, NH, B_SZ);
    fattn_kernel<<<agrid, 128, A_SMEM>>>(Qh, Ql, Kh, Kl, Vth, Vtl, xbh, xbl);

    // 6: output projection
    hmma_gemm_kernel<<<dim3(16, 32), 256, G_SMEM>>>(
        xbh, xbl, 2048, wbh + OFF_O, wbl + OFF_O,
        out, nullptr, nullptr, nullptr, 0, 2048, 2048, 2048);
}